// round 8
// baseline (speedup 1.0000x reference)
#include <cuda_runtime.h>
#include <cuda_bf16.h>
#include <cuda_fp16.h>
#include <cstdint>

#define N_NODES 50000
#define N_EDGES 800000
#define TWO_N   100000
#define TWO_E   1600000
#define SCAN_BLK 1024
#define SCAN_NBLK ((TWO_N + SCAN_BLK - 1) / SCAN_BLK)   // 98

// ---------------- scratch ----------------------------------------------------
__device__ __align__(16) __half g_xwh[N_NODES * 256];     // fp16 xw (gather copy)
__device__ __align__(16) float g_att[N_NODES * 32];       // [s0(8) d0(8) s1(8) d1(8)]
__device__ __align__(16) __nv_bfloat16 g_Whi[256 * 256];  // [k][n] n: [W0|W1]
__device__ __align__(16) __nv_bfloat16 g_Wlo[256 * 256];
__device__ int   g_deg[TWO_N];
__device__ int   g_off[TWO_N + 1];
__device__ int   g_cur[TWO_N];
__device__ int   g_srcarr[TWO_E];
__device__ int   g_bsum[SCAN_NBLK];
__device__ int   g_bsum_scan[SCAN_NBLK];

__device__ __forceinline__ uint32_t smem_u32(const void* p) {
    uint32_t a;
    asm("{ .reg .u64 t; cvta.to.shared.u64 t, %1; cvt.u32.u64 %0, t; }"
        : "=r"(a) : "l"(p));
    return a;
}

// ---------------- W split kernel ---------------------------------------------
__global__ void wsplit_kernel(const float* __restrict__ W0,
                              const float* __restrict__ W1) {
    int i = blockIdx.x * 256 + threadIdx.x;
    int k = i >> 8, n = i & 255;
    float v = (n < 128) ? W0[k * 128 + n] : W1[k * 128 + (n - 128)];
    __nv_bfloat16 h = __float2bfloat16(v);
    g_Whi[i] = h;
    g_Wlo[i] = __float2bfloat16(v - __bfloat162float(h));
}

// ---------------- HMMA GEMM (split-bf16, 3 terms) + logits epilogue ----------
#define APAD 40
#define BPAD 136

__global__ __launch_bounds__(256) void gemm_hmma_kernel(
        const float* __restrict__ x,
        const float* __restrict__ as0, const float* __restrict__ ad0,
        const float* __restrict__ as1, const float* __restrict__ ad1) {
    __shared__ __nv_bfloat16 sAh[128][APAD];
    __shared__ __nv_bfloat16 sAl[128][APAD];
    __shared__ __nv_bfloat16 sBh[32][BPAD];
    __shared__ __nv_bfloat16 sBl[32][BPAD];

    int tid  = threadIdx.x;
    int wid  = tid >> 5;
    int lane = tid & 31;
    int m0   = blockIdx.x * 128;
    int half_ = blockIdx.y;
    int m0w  = (wid >> 1) * 32;
    int n0w  = (wid & 1) * 64;

    float acc[2][8][4];
#pragma unroll
    for (int a = 0; a < 2; a++)
#pragma unroll
        for (int b = 0; b < 8; b++)
#pragma unroll
            for (int c = 0; c < 4; c++) acc[a][b][c] = 0.f;

    int arow = tid >> 1, akb = (tid & 1) * 16;
    bool aok = (m0 + arow) < N_NODES;
    int bk = tid >> 3, bnb = (tid & 7) * 16;

    int a_roff = ((lane >> 3) & 1) * 8 + (lane & 7);
    int a_coff = ((lane >> 4) & 1) * 8;
    int b_koff = ((lane >> 3) & 1) * 8 + (lane & 7);
    int b_noff = ((lane >> 4) & 1) * 8;

    for (int kc = 0; kc < 8; kc++) {
        if (kc > 0) __syncthreads();
        {
            const float* src = x + (size_t)(m0 + arow) * 256 + kc * 32 + akb;
#pragma unroll
            for (int i = 0; i < 16; i += 4) {
                float4 v = aok ? *(const float4*)(src + i)
                               : make_float4(0.f, 0.f, 0.f, 0.f);
                float fv[4] = {v.x, v.y, v.z, v.w};
                uint32_t ph[2], pl[2];
#pragma unroll
                for (int j = 0; j < 2; j++) {
                    __nv_bfloat16 h0 = __float2bfloat16(fv[2*j]);
                    __nv_bfloat16 h1 = __float2bfloat16(fv[2*j+1]);
                    __nv_bfloat16 l0 = __float2bfloat16(fv[2*j]   - __bfloat162float(h0));
                    __nv_bfloat16 l1 = __float2bfloat16(fv[2*j+1] - __bfloat162float(h1));
                    ph[j] = (uint32_t)__bfloat16_as_ushort(h0)
                          | ((uint32_t)__bfloat16_as_ushort(h1) << 16);
                    pl[j] = (uint32_t)__bfloat16_as_ushort(l0)
                          | ((uint32_t)__bfloat16_as_ushort(l1) << 16);
                }
                *(uint2*)&sAh[arow][akb + i] = make_uint2(ph[0], ph[1]);
                *(uint2*)&sAl[arow][akb + i] = make_uint2(pl[0], pl[1]);
            }
        }
        {
            const __nv_bfloat16* wh = g_Whi + (size_t)(kc * 32 + bk) * 256 + half_ * 128 + bnb;
            const __nv_bfloat16* wl = g_Wlo + (size_t)(kc * 32 + bk) * 256 + half_ * 128 + bnb;
            uint4 vh0 = *(const uint4*)wh;
            uint4 vh1 = *(const uint4*)(wh + 8);
            uint4 vl0 = *(const uint4*)wl;
            uint4 vl1 = *(const uint4*)(wl + 8);
            *(uint4*)&sBh[bk][bnb]     = vh0;
            *(uint4*)&sBh[bk][bnb + 8] = vh1;
            *(uint4*)&sBl[bk][bnb]     = vl0;
            *(uint4*)&sBl[bk][bnb + 8] = vl1;
        }
        __syncthreads();

#pragma unroll
        for (int ks = 0; ks < 2; ks++) {
            int k0 = ks * 16;
            uint32_t ah[2][4], al[2][4], bb[4][4];
#pragma unroll
            for (int mt = 0; mt < 2; mt++) {
                uint32_t adrh = smem_u32(&sAh[m0w + mt * 16 + a_roff][k0 + a_coff]);
                asm volatile("ldmatrix.sync.aligned.m8n8.x4.shared.b16 {%0,%1,%2,%3}, [%4];"
                    : "=r"(ah[mt][0]), "=r"(ah[mt][1]), "=r"(ah[mt][2]), "=r"(ah[mt][3])
                    : "r"(adrh));
                uint32_t adrl = smem_u32(&sAl[m0w + mt * 16 + a_roff][k0 + a_coff]);
                asm volatile("ldmatrix.sync.aligned.m8n8.x4.shared.b16 {%0,%1,%2,%3}, [%4];"
                    : "=r"(al[mt][0]), "=r"(al[mt][1]), "=r"(al[mt][2]), "=r"(al[mt][3])
                    : "r"(adrl));
            }
#pragma unroll
            for (int p = 0; p < 4; p++) {
                uint32_t adr = smem_u32(&sBh[k0 + b_koff][n0w + p * 16 + b_noff]);
                asm volatile("ldmatrix.sync.aligned.m8n8.x4.trans.shared.b16 {%0,%1,%2,%3}, [%4];"
                    : "=r"(bb[p][0]), "=r"(bb[p][1]), "=r"(bb[p][2]), "=r"(bb[p][3])
                    : "r"(adr));
            }
#pragma unroll
            for (int mt = 0; mt < 2; mt++)
#pragma unroll
                for (int nt = 0; nt < 8; nt++) {
                    uint32_t b0 = bb[nt >> 1][(nt & 1) * 2];
                    uint32_t b1 = bb[nt >> 1][(nt & 1) * 2 + 1];
                    float* d = acc[mt][nt];
                    asm volatile(
                        "mma.sync.aligned.m16n8k16.row.col.f32.bf16.bf16.f32 "
                        "{%0,%1,%2,%3}, {%4,%5,%6,%7}, {%8,%9}, {%0,%1,%2,%3};"
                        : "+f"(d[0]), "+f"(d[1]), "+f"(d[2]), "+f"(d[3])
                        : "r"(ah[mt][0]), "r"(ah[mt][1]), "r"(ah[mt][2]), "r"(ah[mt][3]),
                          "r"(b0), "r"(b1));
                    asm volatile(
                        "mma.sync.aligned.m16n8k16.row.col.f32.bf16.bf16.f32 "
                        "{%0,%1,%2,%3}, {%4,%5,%6,%7}, {%8,%9}, {%0,%1,%2,%3};"
                        : "+f"(d[0]), "+f"(d[1]), "+f"(d[2]), "+f"(d[3])
                        : "r"(al[mt][0]), "r"(al[mt][1]), "r"(al[mt][2]), "r"(al[mt][3]),
                          "r"(b0), "r"(b1));
                }
#pragma unroll
            for (int p = 0; p < 4; p++) {
                uint32_t adr = smem_u32(&sBl[k0 + b_koff][n0w + p * 16 + b_noff]);
                asm volatile("ldmatrix.sync.aligned.m8n8.x4.trans.shared.b16 {%0,%1,%2,%3}, [%4];"
                    : "=r"(bb[p][0]), "=r"(bb[p][1]), "=r"(bb[p][2]), "=r"(bb[p][3])
                    : "r"(adr));
            }
#pragma unroll
            for (int mt = 0; mt < 2; mt++)
#pragma unroll
                for (int nt = 0; nt < 8; nt++) {
                    uint32_t b0 = bb[nt >> 1][(nt & 1) * 2];
                    uint32_t b1 = bb[nt >> 1][(nt & 1) * 2 + 1];
                    float* d = acc[mt][nt];
                    asm volatile(
                        "mma.sync.aligned.m16n8k16.row.col.f32.bf16.bf16.f32 "
                        "{%0,%1,%2,%3}, {%4,%5,%6,%7}, {%8,%9}, {%0,%1,%2,%3};"
                        : "+f"(d[0]), "+f"(d[1]), "+f"(d[2]), "+f"(d[3])
                        : "r"(ah[mt][0]), "r"(ah[mt][1]), "r"(ah[mt][2]), "r"(ah[mt][3]),
                          "r"(b0), "r"(b1));
                }
        }
    }

    // ---- epilogue: store xw as fp16 + attention logits ----
#pragma unroll
    for (int mt = 0; mt < 2; mt++) {
        int r0 = m0 + m0w + mt * 16 + (lane >> 2);
        int r1 = r0 + 8;
        bool ok0 = r0 < N_NODES, ok1 = r1 < N_NODES;
#pragma unroll
        for (int nt = 0; nt < 8; nt++) {
            int col = half_ * 128 + n0w + nt * 8 + (lane & 3) * 2;
            if (ok0) {
                __half2 h = __floats2half2_rn(acc[mt][nt][0], acc[mt][nt][1]);
                *(__half2*)&g_xwh[(size_t)r0 * 256 + col] = h;
            }
            if (ok1) {
                __half2 h = __floats2half2_rn(acc[mt][nt][2], acc[mt][nt][3]);
                *(__half2*)&g_xwh[(size_t)r1 * 256 + col] = h;
            }
        }
    }

    const float* asv = half_ ? as1 : as0;
    const float* adv = half_ ? ad1 : ad0;
    float asr[16], adr_[16];
#pragma unroll
    for (int nt = 0; nt < 8; nt++) {
        int c = n0w + nt * 8 + (lane & 3) * 2;
        asr[nt * 2]     = asv[c];
        asr[nt * 2 + 1] = asv[c + 1];
        adr_[nt * 2]     = adv[c];
        adr_[nt * 2 + 1] = adv[c + 1];
    }
#pragma unroll
    for (int mt = 0; mt < 2; mt++) {
#pragma unroll
        for (int rh = 0; rh < 2; rh++) {
            float ps[4] = {0.f, 0.f, 0.f, 0.f};
            float pd[4] = {0.f, 0.f, 0.f, 0.f};
#pragma unroll
            for (int nt = 0; nt < 8; nt++) {
                int h = nt >> 1;
                float a0 = acc[mt][nt][rh * 2];
                float a1 = acc[mt][nt][rh * 2 + 1];
                ps[h] += a0 * asr[nt * 2] + a1 * asr[nt * 2 + 1];
                pd[h] += a0 * adr_[nt * 2] + a1 * adr_[nt * 2 + 1];
            }
#pragma unroll
            for (int off = 1; off < 4; off <<= 1) {
#pragma unroll
                for (int h = 0; h < 4; h++) {
                    ps[h] += __shfl_xor_sync(0xffffffffu, ps[h], off);
                    pd[h] += __shfl_xor_sync(0xffffffffu, pd[h], off);
                }
            }
            int r = m0 + m0w + mt * 16 + rh * 8 + (lane >> 2);
            if ((lane & 3) == 0 && r < N_NODES) {
#pragma unroll
                for (int h = 0; h < 4; h++) {
                    int gh = (n0w >> 4) + h;
                    g_att[r * 32 + half_ * 16 + gh]     = ps[h];
                    g_att[r * 32 + half_ * 16 + 8 + gh] = pd[h];
                }
            }
        }
    }
}

// ---------------- zero degree counters ---------------------------------------
__global__ void zero_kernel() {
    int i = blockIdx.x * blockDim.x + threadIdx.x;
    if (i < TWO_N) g_deg[i] = 0;
}

// ---------------- count in-degrees, 4 edges/thread ---------------------------
__global__ void count_kernel(const int* __restrict__ row,
                             const int* __restrict__ col) {
    int base = (blockIdx.x * blockDim.x + threadIdx.x) * 4;
    int d0[4];
#pragma unroll
    for (int i = 0; i < 4; i++) {
        int e = base + i;
        d0[i] = (e < N_EDGES) ? col[e] : -1;
    }
#pragma unroll
    for (int i = 0; i < 4; i++)
        if (d0[i] >= 0) atomicAdd(&g_deg[d0[i]], 1);
    int d1[4];
#pragma unroll
    for (int i = 0; i < 4; i++) d1[i] = (d0[i] >= 0) ? col[d0[i]] : -1;
#pragma unroll
    for (int i = 0; i < 4; i++)
        if (d1[i] >= 0) atomicAdd(&g_deg[N_NODES + d1[i]], 1);
}

// ---------------- exclusive scan (3 stages) ----------------------------------
__global__ void scanA_kernel() {
    __shared__ int sh[SCAN_BLK];
    int t = threadIdx.x;
    int i = blockIdx.x * SCAN_BLK + t;
    int v = (i < TWO_N) ? g_deg[i] : 0;
    sh[t] = v;
    __syncthreads();
    for (int off = 1; off < SCAN_BLK; off <<= 1) {
        int add = (t >= off) ? sh[t - off] : 0;
        __syncthreads();
        sh[t] += add;
        __syncthreads();
    }
    if (i < TWO_N) g_off[i] = sh[t] - v;
    if (t == SCAN_BLK - 1) g_bsum[blockIdx.x] = sh[SCAN_BLK - 1];
}

__global__ void scanB_kernel() {
    __shared__ int sh[128];
    int t = threadIdx.x;
    int v = (t < SCAN_NBLK) ? g_bsum[t] : 0;
    sh[t] = v;
    __syncthreads();
    for (int off = 1; off < 128; off <<= 1) {
        int add = (t >= off) ? sh[t - off] : 0;
        __syncthreads();
        sh[t] += add;
        __syncthreads();
    }
    if (t < SCAN_NBLK) g_bsum_scan[t] = sh[t] - v;
}

__global__ void scanC_kernel() {
    int i = blockIdx.x * SCAN_BLK + threadIdx.x;
    if (i < TWO_N) {
        int v = g_off[i] + g_bsum_scan[blockIdx.x];
        g_off[i] = v;
        g_cur[i] = v;
    }
    if (i == 0) g_off[TWO_N] = TWO_E;
}

// ---------------- scatter into CSR, 4 edges/thread ---------------------------
__global__ void scatter_kernel(const int* __restrict__ row,
                               const int* __restrict__ col) {
    int base = (blockIdx.x * blockDim.x + threadIdx.x) * 4;
    int r0[4], d0[4];
#pragma unroll
    for (int i = 0; i < 4; i++) {
        int e = base + i;
        if (e < N_EDGES) { r0[i] = row[e]; d0[i] = col[e]; }
        else { r0[i] = -1; d0[i] = -1; }
    }
#pragma unroll
    for (int i = 0; i < 4; i++) {
        if (d0[i] >= 0) {
            int p = atomicAdd(&g_cur[d0[i]], 1);
            g_srcarr[p] = r0[i];
        }
    }
    int r1[4], d1[4];
#pragma unroll
    for (int i = 0; i < 4; i++) {
        if (d0[i] >= 0) { r1[i] = row[d0[i]]; d1[i] = col[d0[i]]; }
        else { r1[i] = -1; d1[i] = -1; }
    }
#pragma unroll
    for (int i = 0; i < 4; i++) {
        if (d1[i] >= 0) {
            int p = atomicAdd(&g_cur[N_NODES + d1[i]], 1);
            g_srcarr[p] = r1[i];
        }
    }
}

// ---------------- fused aggregation + residual + LayerNorm -------------------
// warp per node; lane covers 4 channels of hop0 (c0) + 4 of hop1 (128+c0).
// Gather reads fp16 xw (half L2 traffic). hop-2 self loop doubled (reference
// appends self-loops twice). No segment-max (shift-invariant softmax, O(1)
// logits).
__global__ void agg_ln_kernel(const float* __restrict__ b0,
                              const float* __restrict__ b1,
                              const float* __restrict__ x,
                              const float* __restrict__ gamma,
                              const float* __restrict__ beta,
                              float* __restrict__ out) {
    int n = (blockIdx.x * blockDim.x + threadIdx.x) >> 5;
    if (n >= N_NODES) return;
    int lane = threadIdx.x & 31;
    int head = lane >> 2;
    int c0 = lane * 4;

    // ---- hop 0 ----
    float ad = g_att[n * 32 + 8 + head];
    float t  = g_att[n * 32 + head] + ad;
    t = (t > 0.f) ? t : 0.2f * t;
    float p = __expf(t);
    float sum0 = p;
    float4 acc0;
    {
        uint2 raw = *(const uint2*)&g_xwh[(size_t)n * 256 + c0];
        float2 f0 = __half22float2(*(__half2*)&raw.x);
        float2 f1 = __half22float2(*(__half2*)&raw.y);
        acc0 = make_float4(p * f0.x, p * f0.y, p * f1.x, p * f1.y);
    }
    int je = g_off[n + 1];
    for (int j = g_off[n]; j < je; j++) {
        int src = g_srcarr[j];
        float tt = g_att[src * 32 + head] + ad;
        tt = (tt > 0.f) ? tt : 0.2f * tt;
        float pp = __expf(tt);
        sum0 += pp;
        uint2 raw = *(const uint2*)&g_xwh[(size_t)src * 256 + c0];
        float2 f0 = __half22float2(*(__half2*)&raw.x);
        float2 f1 = __half22float2(*(__half2*)&raw.y);
        acc0.x += pp * f0.x; acc0.y += pp * f0.y;
        acc0.z += pp * f1.x; acc0.w += pp * f1.y;
    }

    // ---- hop 1 (self doubled) ----
    ad = g_att[n * 32 + 24 + head];
    t  = g_att[n * 32 + 16 + head] + ad;
    t = (t > 0.f) ? t : 0.2f * t;
    p = 2.0f * __expf(t);
    float sum1 = p;
    float4 acc1;
    {
        uint2 raw = *(const uint2*)&g_xwh[(size_t)n * 256 + 128 + c0];
        float2 f0 = __half22float2(*(__half2*)&raw.x);
        float2 f1 = __half22float2(*(__half2*)&raw.y);
        acc1 = make_float4(p * f0.x, p * f0.y, p * f1.x, p * f1.y);
    }
    je = g_off[N_NODES + n + 1];
    for (int j = g_off[N_NODES + n]; j < je; j++) {
        int src = g_srcarr[j];
        float tt = g_att[src * 32 + 16 + head] + ad;
        tt = (tt > 0.f) ? tt : 0.2f * tt;
        float pp = __expf(tt);
        sum1 += pp;
        uint2 raw = *(const uint2*)&g_xwh[(size_t)src * 256 + 128 + c0];
        float2 f0 = __half22float2(*(__half2*)&raw.x);
        float2 f1 = __half22float2(*(__half2*)&raw.y);
        acc1.x += pp * f0.x; acc1.y += pp * f0.y;
        acc1.z += pp * f1.x; acc1.w += pp * f1.y;
    }

    // ---- bias + residual + LN ----
    float i0 = 1.f / sum0, i1 = 1.f / sum1;
    float4 bb0 = *(const float4*)&b0[c0];
    float4 bb1 = *(const float4*)&b1[c0];
    float4 x0 = *(const float4*)&x[n * 256 + c0];
    float4 x1 = *(const float4*)&x[n * 256 + 128 + c0];
    float vv[8];
    vv[0] = acc0.x * i0 + bb0.x + x0.x;
    vv[1] = acc0.y * i0 + bb0.y + x0.y;
    vv[2] = acc0.z * i0 + bb0.z + x0.z;
    vv[3] = acc0.w * i0 + bb0.w + x0.w;
    vv[4] = acc1.x * i1 + bb1.x + x1.x;
    vv[5] = acc1.y * i1 + bb1.y + x1.y;
    vv[6] = acc1.z * i1 + bb1.z + x1.z;
    vv[7] = acc1.w * i1 + bb1.w + x1.w;

    float s = 0.f, s2 = 0.f;
#pragma unroll
    for (int i = 0; i < 8; i++) { s += vv[i]; s2 += vv[i] * vv[i]; }
#pragma unroll
    for (int off = 16; off > 0; off >>= 1) {
        s  += __shfl_xor_sync(0xffffffffu, s, off);
        s2 += __shfl_xor_sync(0xffffffffu, s2, off);
    }
    float mean = s * (1.f / 256.f);
    float var  = s2 * (1.f / 256.f) - mean * mean;
    float rs   = rsqrtf(var + 1e-5f);

    float4 g0 = *(const float4*)&gamma[c0];
    float4 g1 = *(const float4*)&gamma[128 + c0];
    float4 be0 = *(const float4*)&beta[c0];
    float4 be1 = *(const float4*)&beta[128 + c0];
    float4 o0, o1;
    o0.x = (vv[0] - mean) * rs * g0.x + be0.x;
    o0.y = (vv[1] - mean) * rs * g0.y + be0.y;
    o0.z = (vv[2] - mean) * rs * g0.z + be0.z;
    o0.w = (vv[3] - mean) * rs * g0.w + be0.w;
    o1.x = (vv[4] - mean) * rs * g1.x + be1.x;
    o1.y = (vv[5] - mean) * rs * g1.y + be1.y;
    o1.z = (vv[6] - mean) * rs * g1.z + be1.z;
    o1.w = (vv[7] - mean) * rs * g1.w + be1.w;
    *(float4*)&out[n * 256 + c0]       = o0;
    *(float4*)&out[n * 256 + 128 + c0] = o1;
}

// ---------------- launch (single stream — R7 overlap regressed) --------------
extern "C" void kernel_launch(void* const* d_in, const int* in_sizes, int n_in,
                              void* d_out, int out_size) {
    const float* x     = (const float*)d_in[0];
    const int*   ei    = (const int*)d_in[1];
    const float* W0    = (const float*)d_in[2];
    const float* as0   = (const float*)d_in[3];
    const float* ad0   = (const float*)d_in[4];
    const float* b0    = (const float*)d_in[5];
    const float* W1    = (const float*)d_in[6];
    const float* as1   = (const float*)d_in[7];
    const float* ad1   = (const float*)d_in[8];
    const float* b1    = (const float*)d_in[9];
    const float* gamma = (const float*)d_in[10];
    const float* beta  = (const float*)d_in[11];
    float* out = (float*)d_out;

    const int* row = ei;
    const int* col = ei + N_EDGES;

    zero_kernel<<<(TWO_N + 255) / 256, 256>>>();
    wsplit_kernel<<<256, 256>>>(W0, W1);
    gemm_hmma_kernel<<<dim3((N_NODES + 127) / 128, 2), 256>>>(x, as0, ad0, as1, ad1);
    count_kernel<<<(N_EDGES / 4 + 255) / 256, 256>>>(row, col);
    scanA_kernel<<<SCAN_NBLK, SCAN_BLK>>>();
    scanB_kernel<<<1, 128>>>();
    scanC_kernel<<<SCAN_NBLK, SCAN_BLK>>>();
    scatter_kernel<<<(N_EDGES / 4 + 255) / 256, 256>>>(row, col);
    agg_ln_kernel<<<(N_NODES * 32 + 255) / 256, 256>>>(b0, b1, x, gamma, beta, out);
}

// round 9
// speedup vs baseline: 1.0281x; 1.0281x over previous
#include <cuda_runtime.h>
#include <cuda_bf16.h>
#include <cstdint>

#define N_NODES 50000
#define N_EDGES 800000
#define TWO_N   100000
#define TWO_E   1600000
#define SCAN_BLK 1024
#define SCAN_NBLK ((TWO_N + SCAN_BLK - 1) / SCAN_BLK)   // 98

// ---------------- scratch ----------------------------------------------------
__device__ __align__(16) float g_xw[N_NODES * 256];   // x @ [W0 | W1]
__device__ __align__(16) float g_att[N_NODES * 32];   // [s0(8) d0(8) s1(8) d1(8)]
__device__ __align__(16) __nv_bfloat16 g_Whi[256 * 256];  // [k][n] n: [W0|W1]
__device__ __align__(16) __nv_bfloat16 g_Wlo[256 * 256];
__device__ int   g_deg[TWO_N];
__device__ int   g_off[TWO_N + 1];
__device__ int   g_cur[TWO_N];
__device__ int   g_srcarr[TWO_E];
__device__ int   g_d1[N_EDGES];          // cached hop-2 dst (col[col[e]])
__device__ int   g_r1[N_EDGES];          // cached hop-2 src (row[col[e]])
__device__ int   g_bsum[SCAN_NBLK];
__device__ int   g_bsum_scan[SCAN_NBLK];

__device__ __forceinline__ uint32_t smem_u32(const void* p) {
    uint32_t a;
    asm("{ .reg .u64 t; cvta.to.shared.u64 t, %1; cvt.u32.u64 %0, t; }"
        : "=r"(a) : "l"(p));
    return a;
}

// ---------------- W split kernel ---------------------------------------------
__global__ void wsplit_kernel(const float* __restrict__ W0,
                              const float* __restrict__ W1) {
    int i = blockIdx.x * 256 + threadIdx.x;
    int k = i >> 8, n = i & 255;
    float v = (n < 128) ? W0[k * 128 + n] : W1[k * 128 + (n - 128)];
    __nv_bfloat16 h = __float2bfloat16(v);
    g_Whi[i] = h;
    g_Wlo[i] = __float2bfloat16(v - __bfloat162float(h));
}

// ---------------- HMMA GEMM (split-bf16, 3 terms) + logits epilogue ----------
#define APAD 40
#define BPAD 136

__global__ __launch_bounds__(256) void gemm_hmma_kernel(
        const float* __restrict__ x,
        const float* __restrict__ as0, const float* __restrict__ ad0,
        const float* __restrict__ as1, const float* __restrict__ ad1) {
    __shared__ __nv_bfloat16 sAh[128][APAD];
    __shared__ __nv_bfloat16 sAl[128][APAD];
    __shared__ __nv_bfloat16 sBh[32][BPAD];
    __shared__ __nv_bfloat16 sBl[32][BPAD];

    int tid  = threadIdx.x;
    int wid  = tid >> 5;
    int lane = tid & 31;
    int m0   = blockIdx.x * 128;
    int half_ = blockIdx.y;
    int m0w  = (wid >> 1) * 32;
    int n0w  = (wid & 1) * 64;

    float acc[2][8][4];
#pragma unroll
    for (int a = 0; a < 2; a++)
#pragma unroll
        for (int b = 0; b < 8; b++)
#pragma unroll
            for (int c = 0; c < 4; c++) acc[a][b][c] = 0.f;

    int arow = tid >> 1, akb = (tid & 1) * 16;
    bool aok = (m0 + arow) < N_NODES;
    int bk = tid >> 3, bnb = (tid & 7) * 16;

    int a_roff = ((lane >> 3) & 1) * 8 + (lane & 7);
    int a_coff = ((lane >> 4) & 1) * 8;
    int b_koff = ((lane >> 3) & 1) * 8 + (lane & 7);
    int b_noff = ((lane >> 4) & 1) * 8;

    for (int kc = 0; kc < 8; kc++) {
        if (kc > 0) __syncthreads();
        {
            const float* src = x + (size_t)(m0 + arow) * 256 + kc * 32 + akb;
#pragma unroll
            for (int i = 0; i < 16; i += 4) {
                float4 v = aok ? *(const float4*)(src + i)
                               : make_float4(0.f, 0.f, 0.f, 0.f);
                float fv[4] = {v.x, v.y, v.z, v.w};
                uint32_t ph[2], pl[2];
#pragma unroll
                for (int j = 0; j < 2; j++) {
                    __nv_bfloat16 h0 = __float2bfloat16(fv[2*j]);
                    __nv_bfloat16 h1 = __float2bfloat16(fv[2*j+1]);
                    __nv_bfloat16 l0 = __float2bfloat16(fv[2*j]   - __bfloat162float(h0));
                    __nv_bfloat16 l1 = __float2bfloat16(fv[2*j+1] - __bfloat162float(h1));
                    ph[j] = (uint32_t)__bfloat16_as_ushort(h0)
                          | ((uint32_t)__bfloat16_as_ushort(h1) << 16);
                    pl[j] = (uint32_t)__bfloat16_as_ushort(l0)
                          | ((uint32_t)__bfloat16_as_ushort(l1) << 16);
                }
                *(uint2*)&sAh[arow][akb + i] = make_uint2(ph[0], ph[1]);
                *(uint2*)&sAl[arow][akb + i] = make_uint2(pl[0], pl[1]);
            }
        }
        {
            const __nv_bfloat16* wh = g_Whi + (size_t)(kc * 32 + bk) * 256 + half_ * 128 + bnb;
            const __nv_bfloat16* wl = g_Wlo + (size_t)(kc * 32 + bk) * 256 + half_ * 128 + bnb;
            uint4 vh0 = *(const uint4*)wh;
            uint4 vh1 = *(const uint4*)(wh + 8);
            uint4 vl0 = *(const uint4*)wl;
            uint4 vl1 = *(const uint4*)(wl + 8);
            *(uint4*)&sBh[bk][bnb]     = vh0;
            *(uint4*)&sBh[bk][bnb + 8] = vh1;
            *(uint4*)&sBl[bk][bnb]     = vl0;
            *(uint4*)&sBl[bk][bnb + 8] = vl1;
        }
        __syncthreads();

#pragma unroll
        for (int ks = 0; ks < 2; ks++) {
            int k0 = ks * 16;
            uint32_t ah[2][4], al[2][4], bb[4][4];
#pragma unroll
            for (int mt = 0; mt < 2; mt++) {
                uint32_t adrh = smem_u32(&sAh[m0w + mt * 16 + a_roff][k0 + a_coff]);
                asm volatile("ldmatrix.sync.aligned.m8n8.x4.shared.b16 {%0,%1,%2,%3}, [%4];"
                    : "=r"(ah[mt][0]), "=r"(ah[mt][1]), "=r"(ah[mt][2]), "=r"(ah[mt][3])
                    : "r"(adrh));
                uint32_t adrl = smem_u32(&sAl[m0w + mt * 16 + a_roff][k0 + a_coff]);
                asm volatile("ldmatrix.sync.aligned.m8n8.x4.shared.b16 {%0,%1,%2,%3}, [%4];"
                    : "=r"(al[mt][0]), "=r"(al[mt][1]), "=r"(al[mt][2]), "=r"(al[mt][3])
                    : "r"(adrl));
            }
#pragma unroll
            for (int p = 0; p < 4; p++) {
                uint32_t adr = smem_u32(&sBh[k0 + b_koff][n0w + p * 16 + b_noff]);
                asm volatile("ldmatrix.sync.aligned.m8n8.x4.trans.shared.b16 {%0,%1,%2,%3}, [%4];"
                    : "=r"(bb[p][0]), "=r"(bb[p][1]), "=r"(bb[p][2]), "=r"(bb[p][3])
                    : "r"(adr));
            }
#pragma unroll
            for (int mt = 0; mt < 2; mt++)
#pragma unroll
                for (int nt = 0; nt < 8; nt++) {
                    uint32_t b0 = bb[nt >> 1][(nt & 1) * 2];
                    uint32_t b1 = bb[nt >> 1][(nt & 1) * 2 + 1];
                    float* d = acc[mt][nt];
                    asm volatile(
                        "mma.sync.aligned.m16n8k16.row.col.f32.bf16.bf16.f32 "
                        "{%0,%1,%2,%3}, {%4,%5,%6,%7}, {%8,%9}, {%0,%1,%2,%3};"
                        : "+f"(d[0]), "+f"(d[1]), "+f"(d[2]), "+f"(d[3])
                        : "r"(ah[mt][0]), "r"(ah[mt][1]), "r"(ah[mt][2]), "r"(ah[mt][3]),
                          "r"(b0), "r"(b1));
                    asm volatile(
                        "mma.sync.aligned.m16n8k16.row.col.f32.bf16.bf16.f32 "
                        "{%0,%1,%2,%3}, {%4,%5,%6,%7}, {%8,%9}, {%0,%1,%2,%3};"
                        : "+f"(d[0]), "+f"(d[1]), "+f"(d[2]), "+f"(d[3])
                        : "r"(al[mt][0]), "r"(al[mt][1]), "r"(al[mt][2]), "r"(al[mt][3]),
                          "r"(b0), "r"(b1));
                }
#pragma unroll
            for (int p = 0; p < 4; p++) {
                uint32_t adr = smem_u32(&sBl[k0 + b_koff][n0w + p * 16 + b_noff]);
                asm volatile("ldmatrix.sync.aligned.m8n8.x4.trans.shared.b16 {%0,%1,%2,%3}, [%4];"
                    : "=r"(bb[p][0]), "=r"(bb[p][1]), "=r"(bb[p][2]), "=r"(bb[p][3])
                    : "r"(adr));
            }
#pragma unroll
            for (int mt = 0; mt < 2; mt++)
#pragma unroll
                for (int nt = 0; nt < 8; nt++) {
                    uint32_t b0 = bb[nt >> 1][(nt & 1) * 2];
                    uint32_t b1 = bb[nt >> 1][(nt & 1) * 2 + 1];
                    float* d = acc[mt][nt];
                    asm volatile(
                        "mma.sync.aligned.m16n8k16.row.col.f32.bf16.bf16.f32 "
                        "{%0,%1,%2,%3}, {%4,%5,%6,%7}, {%8,%9}, {%0,%1,%2,%3};"
                        : "+f"(d[0]), "+f"(d[1]), "+f"(d[2]), "+f"(d[3])
                        : "r"(ah[mt][0]), "r"(ah[mt][1]), "r"(ah[mt][2]), "r"(ah[mt][3]),
                          "r"(b0), "r"(b1));
                }
        }
    }

    // ---- epilogue: store xw + attention logits ----
#pragma unroll
    for (int mt = 0; mt < 2; mt++) {
        int r0 = m0 + m0w + mt * 16 + (lane >> 2);
        int r1 = r0 + 8;
        bool ok0 = r0 < N_NODES, ok1 = r1 < N_NODES;
#pragma unroll
        for (int nt = 0; nt < 8; nt++) {
            int col = half_ * 128 + n0w + nt * 8 + (lane & 3) * 2;
            if (ok0) *(float2*)&g_xw[(size_t)r0 * 256 + col] =
                make_float2(acc[mt][nt][0], acc[mt][nt][1]);
            if (ok1) *(float2*)&g_xw[(size_t)r1 * 256 + col] =
                make_float2(acc[mt][nt][2], acc[mt][nt][3]);
        }
    }

    const float* asv = half_ ? as1 : as0;
    const float* adv = half_ ? ad1 : ad0;
    float asr[16], adr_[16];
#pragma unroll
    for (int nt = 0; nt < 8; nt++) {
        int c = n0w + nt * 8 + (lane & 3) * 2;
        asr[nt * 2]     = asv[c];
        asr[nt * 2 + 1] = asv[c + 1];
        adr_[nt * 2]     = adv[c];
        adr_[nt * 2 + 1] = adv[c + 1];
    }
#pragma unroll
    for (int mt = 0; mt < 2; mt++) {
#pragma unroll
        for (int rh = 0; rh < 2; rh++) {
            float ps[4] = {0.f, 0.f, 0.f, 0.f};
            float pd[4] = {0.f, 0.f, 0.f, 0.f};
#pragma unroll
            for (int nt = 0; nt < 8; nt++) {
                int h = nt >> 1;
                float a0 = acc[mt][nt][rh * 2];
                float a1 = acc[mt][nt][rh * 2 + 1];
                ps[h] += a0 * asr[nt * 2] + a1 * asr[nt * 2 + 1];
                pd[h] += a0 * adr_[nt * 2] + a1 * adr_[nt * 2 + 1];
            }
#pragma unroll
            for (int off = 1; off < 4; off <<= 1) {
#pragma unroll
                for (int h = 0; h < 4; h++) {
                    ps[h] += __shfl_xor_sync(0xffffffffu, ps[h], off);
                    pd[h] += __shfl_xor_sync(0xffffffffu, pd[h], off);
                }
            }
            int r = m0 + m0w + mt * 16 + rh * 8 + (lane >> 2);
            if ((lane & 3) == 0 && r < N_NODES) {
#pragma unroll
                for (int h = 0; h < 4; h++) {
                    int gh = (n0w >> 4) + h;
                    g_att[r * 32 + half_ * 16 + gh]     = ps[h];
                    g_att[r * 32 + half_ * 16 + 8 + gh] = pd[h];
                }
            }
        }
    }
}

// ---------------- zero degree counters ---------------------------------------
__global__ void zero_kernel() {
    int i = blockIdx.x * blockDim.x + threadIdx.x;
    if (i < TWO_N) g_deg[i] = 0;
}

// ---------------- count in-degrees + cache hop-2 chase (1 edge/thread) -------
__global__ void count_kernel(const int* __restrict__ row,
                             const int* __restrict__ col) {
    int e = blockIdx.x * blockDim.x + threadIdx.x;
    if (e >= N_EDGES) return;
    int d0 = col[e];
    atomicAdd(&g_deg[d0], 1);
    int d1 = col[d0];
    int r1 = row[d0];
    g_d1[e] = d1;
    g_r1[e] = r1;
    atomicAdd(&g_deg[N_NODES + d1], 1);
}

// ---------------- exclusive scan (3 stages) ----------------------------------
__global__ void scanA_kernel() {
    __shared__ int sh[SCAN_BLK];
    int t = threadIdx.x;
    int i = blockIdx.x * SCAN_BLK + t;
    int v = (i < TWO_N) ? g_deg[i] : 0;
    sh[t] = v;
    __syncthreads();
    for (int off = 1; off < SCAN_BLK; off <<= 1) {
        int add = (t >= off) ? sh[t - off] : 0;
        __syncthreads();
        sh[t] += add;
        __syncthreads();
    }
    if (i < TWO_N) g_off[i] = sh[t] - v;
    if (t == SCAN_BLK - 1) g_bsum[blockIdx.x] = sh[SCAN_BLK - 1];
}

__global__ void scanB_kernel() {
    __shared__ int sh[128];
    int t = threadIdx.x;
    int v = (t < SCAN_NBLK) ? g_bsum[t] : 0;
    sh[t] = v;
    __syncthreads();
    for (int off = 1; off < 128; off <<= 1) {
        int add = (t >= off) ? sh[t - off] : 0;
        __syncthreads();
        sh[t] += add;
        __syncthreads();
    }
    if (t < SCAN_NBLK) g_bsum_scan[t] = sh[t] - v;
}

__global__ void scanC_kernel() {
    int i = blockIdx.x * SCAN_BLK + threadIdx.x;
    if (i < TWO_N) {
        int v = g_off[i] + g_bsum_scan[blockIdx.x];
        g_off[i] = v;
        g_cur[i] = v;
    }
    if (i == 0) g_off[TWO_N] = TWO_E;
}

// ---------------- scatter into CSR (coalesced reads only; 1 edge/thread) -----
__global__ void scatter_kernel(const int* __restrict__ row,
                               const int* __restrict__ col) {
    int e = blockIdx.x * blockDim.x + threadIdx.x;
    if (e >= N_EDGES) return;
    int r0 = row[e];
    int d0 = col[e];
    int p = atomicAdd(&g_cur[d0], 1);
    g_srcarr[p] = r0;
    int d1 = g_d1[e];          // cached in count_kernel (coalesced read)
    int r1 = g_r1[e];
    p = atomicAdd(&g_cur[N_NODES + d1], 1);
    g_srcarr[p] = r1;
}

// ---------------- fused aggregation + residual + LayerNorm -------------------
// warp per node; lane covers 4 channels of hop0 (c0) + 4 of hop1 (128+c0).
// hop-2 self loop doubled (reference appends self-loops twice).
// No segment-max (O(1) logits; softmax shift-invariant). Edge loop manually
// unrolled x2 to raise MLP on the src/att/xw load chains.
__global__ void agg_ln_kernel(const float* __restrict__ b0,
                              const float* __restrict__ b1,
                              const float* __restrict__ x,
                              const float* __restrict__ gamma,
                              const float* __restrict__ beta,
                              float* __restrict__ out) {
    int n = (blockIdx.x * blockDim.x + threadIdx.x) >> 5;
    if (n >= N_NODES) return;
    int lane = threadIdx.x & 31;
    int head = lane >> 2;
    int c0 = lane * 4;

    // ---- hop 0 ----
    float ad = g_att[n * 32 + 8 + head];
    float t  = g_att[n * 32 + head] + ad;
    t = (t > 0.f) ? t : 0.2f * t;
    float p = __expf(t);
    float sum0 = p;
    float4 v = *(const float4*)&g_xw[n * 256 + c0];
    float4 acc0 = make_float4(p * v.x, p * v.y, p * v.z, p * v.w);
    {
        int jb = g_off[n], je = g_off[n + 1];
        int j = jb;
        for (; j + 2 <= je; j += 2) {
            int s0 = g_srcarr[j];
            int s1 = g_srcarr[j + 1];
            float ta = g_att[s0 * 32 + head] + ad;
            float tb = g_att[s1 * 32 + head] + ad;
            float4 wa = *(const float4*)&g_xw[s0 * 256 + c0];
            float4 wb = *(const float4*)&g_xw[s1 * 256 + c0];
            ta = (ta > 0.f) ? ta : 0.2f * ta;
            tb = (tb > 0.f) ? tb : 0.2f * tb;
            float pa = __expf(ta);
            float pb = __expf(tb);
            sum0 += pa + pb;
            acc0.x += pa * wa.x + pb * wb.x;
            acc0.y += pa * wa.y + pb * wb.y;
            acc0.z += pa * wa.z + pb * wb.z;
            acc0.w += pa * wa.w + pb * wb.w;
        }
        if (j < je) {
            int s0 = g_srcarr[j];
            float ta = g_att[s0 * 32 + head] + ad;
            float4 wa = *(const float4*)&g_xw[s0 * 256 + c0];
            ta = (ta > 0.f) ? ta : 0.2f * ta;
            float pa = __expf(ta);
            sum0 += pa;
            acc0.x += pa * wa.x; acc0.y += pa * wa.y;
            acc0.z += pa * wa.z; acc0.w += pa * wa.w;
        }
    }

    // ---- hop 1 (self doubled) ----
    ad = g_att[n * 32 + 24 + head];
    t  = g_att[n * 32 + 16 + head] + ad;
    t = (t > 0.f) ? t : 0.2f * t;
    p = 2.0f * __expf(t);
    float sum1 = p;
    v = *(const float4*)&g_xw[n * 256 + 128 + c0];
    float4 acc1 = make_float4(p * v.x, p * v.y, p * v.z, p * v.w);
    {
        int jb = g_off[N_NODES + n], je = g_off[N_NODES + n + 1];
        int j = jb;
        for (; j + 2 <= je; j += 2) {
            int s0 = g_srcarr[j];
            int s1 = g_srcarr[j + 1];
            float ta = g_att[s0 * 32 + 16 + head] + ad;
            float tb = g_att[s1 * 32 + 16 + head] + ad;
            float4 wa = *(const float4*)&g_xw[s0 * 256 + 128 + c0];
            float4 wb = *(const float4*)&g_xw[s1 * 256 + 128 + c0];
            ta = (ta > 0.f) ? ta : 0.2f * ta;
            tb = (tb > 0.f) ? tb : 0.2f * tb;
            float pa = __expf(ta);
            float pb = __expf(tb);
            sum1 += pa + pb;
            acc1.x += pa * wa.x + pb * wb.x;
            acc1.y += pa * wa.y + pb * wb.y;
            acc1.z += pa * wa.z + pb * wb.z;
            acc1.w += pa * wa.w + pb * wb.w;
        }
        if (j < je) {
            int s0 = g_srcarr[j];
            float ta = g_att[s0 * 32 + 16 + head] + ad;
            float4 wa = *(const float4*)&g_xw[s0 * 256 + 128 + c0];
            ta = (ta > 0.f) ? ta : 0.2f * ta;
            float pa = __expf(ta);
            sum1 += pa;
            acc1.x += pa * wa.x; acc1.y += pa * wa.y;
            acc1.z += pa * wa.z; acc1.w += pa * wa.w;
        }
    }

    // ---- bias + residual + LN ----
    float i0 = 1.f / sum0, i1 = 1.f / sum1;
    float4 bb0 = *(const float4*)&b0[c0];
    float4 bb1 = *(const float4*)&b1[c0];
    float4 x0 = *(const float4*)&x[n * 256 + c0];
    float4 x1 = *(const float4*)&x[n * 256 + 128 + c0];
    float vv[8];
    vv[0] = acc0.x * i0 + bb0.x + x0.x;
    vv[1] = acc0.y * i0 + bb0.y + x0.y;
    vv[2] = acc0.z * i0 + bb0.z + x0.z;
    vv[3] = acc0.w * i0 + bb0.w + x0.w;
    vv[4] = acc1.x * i1 + bb1.x + x1.x;
    vv[5] = acc1.y * i1 + bb1.y + x1.y;
    vv[6] = acc1.z * i1 + bb1.z + x1.z;
    vv[7] = acc1.w * i1 + bb1.w + x1.w;

    float s = 0.f, s2 = 0.f;
#pragma unroll
    for (int i = 0; i < 8; i++) { s += vv[i]; s2 += vv[i] * vv[i]; }
#pragma unroll
    for (int off = 16; off > 0; off >>= 1) {
        s  += __shfl_xor_sync(0xffffffffu, s, off);
        s2 += __shfl_xor_sync(0xffffffffu, s2, off);
    }
    float mean = s * (1.f / 256.f);
    float var  = s2 * (1.f / 256.f) - mean * mean;
    float rs   = rsqrtf(var + 1e-5f);

    float4 g0 = *(const float4*)&gamma[c0];
    float4 g1 = *(const float4*)&gamma[128 + c0];
    float4 be0 = *(const float4*)&beta[c0];
    float4 be1 = *(const float4*)&beta[128 + c0];
    float4 o0, o1;
    o0.x = (vv[0] - mean) * rs * g0.x + be0.x;
    o0.y = (vv[1] - mean) * rs * g0.y + be0.y;
    o0.z = (vv[2] - mean) * rs * g0.z + be0.z;
    o0.w = (vv[3] - mean) * rs * g0.w + be0.w;
    o1.x = (vv[4] - mean) * rs * g1.x + be1.x;
    o1.y = (vv[5] - mean) * rs * g1.y + be1.y;
    o1.z = (vv[6] - mean) * rs * g1.z + be1.z;
    o1.w = (vv[7] - mean) * rs * g1.w + be1.w;
    *(float4*)&out[n * 256 + c0]       = o0;
    *(float4*)&out[n * 256 + 128 + c0] = o1;
}

// ---------------- launch (single stream) -------------------------------------
extern "C" void kernel_launch(void* const* d_in, const int* in_sizes, int n_in,
                              void* d_out, int out_size) {
    const float* x     = (const float*)d_in[0];
    const int*   ei    = (const int*)d_in[1];
    const float* W0    = (const float*)d_in[2];
    const float* as0   = (const float*)d_in[3];
    const float* ad0   = (const float*)d_in[4];
    const float* b0    = (const float*)d_in[5];
    const float* W1    = (const float*)d_in[6];
    const float* as1   = (const float*)d_in[7];
    const float* ad1   = (const float*)d_in[8];
    const float* b1    = (const float*)d_in[9];
    const float* gamma = (const float*)d_in[10];
    const float* beta  = (const float*)d_in[11];
    float* out = (float*)d_out;

    const int* row = ei;
    const int* col = ei + N_EDGES;

    zero_kernel<<<(TWO_N + 255) / 256, 256>>>();
    wsplit_kernel<<<256, 256>>>(W0, W1);
    gemm_hmma_kernel<<<dim3((N_NODES + 127) / 128, 2), 256>>>(x, as0, ad0, as1, ad1);
    count_kernel<<<(N_EDGES + 255) / 256, 256>>>(row, col);
    scanA_kernel<<<SCAN_NBLK, SCAN_BLK>>>();
    scanB_kernel<<<1, 128>>>();
    scanC_kernel<<<SCAN_NBLK, SCAN_BLK>>>();
    scatter_kernel<<<(N_EDGES + 255) / 256, 256>>>(row, col);
    agg_ln_kernel<<<(N_NODES * 32 + 255) / 256, 256>>>(b0, b1, x, gamma, beta, out);
}

// round 10
// speedup vs baseline: 1.4956x; 1.4547x over previous
#include <cuda_runtime.h>
#include <cuda_bf16.h>
#include <cstdint>

#define N_NODES 50000
#define N_EDGES 800000
#define TWO_N   100000
#define TWO_E   1600000
#define SCAN_BLK 1024
#define SCAN_NBLK ((TWO_N + SCAN_BLK - 1) / SCAN_BLK)   // 98

// ---------------- scratch ----------------------------------------------------
__device__ __align__(16) float g_xw[N_NODES * 256];   // x @ [W0 | W1]
__device__ __align__(16) float g_att[N_NODES * 32];   // [s0(8) d0(8) s1(8) d1(8)]
__device__ __align__(16) __nv_bfloat16 g_Whi[256 * 256];  // [k][n] n: [W0|W1]
__device__ __align__(16) __nv_bfloat16 g_Wlo[256 * 256];
__device__ int   g_deg[TWO_N];
__device__ int   g_off[TWO_N + 1];
__device__ int   g_cur[TWO_N];
__device__ int   g_srcarr[TWO_E];
__device__ int   g_bsum[SCAN_NBLK];
__device__ int   g_bsum_scan[SCAN_NBLK];

__device__ __forceinline__ uint32_t smem_u32(const void* p) {
    uint32_t a;
    asm("{ .reg .u64 t; cvta.to.shared.u64 t, %1; cvt.u32.u64 %0, t; }"
        : "=r"(a) : "l"(p));
    return a;
}

// ---------------- W split kernel ---------------------------------------------
__global__ void wsplit_kernel(const float* __restrict__ W0,
                              const float* __restrict__ W1) {
    int i = blockIdx.x * 256 + threadIdx.x;      // over [k][n], n in [0,256)
    int k = i >> 8, n = i & 255;
    float v = (n < 128) ? W0[k * 128 + n] : W1[k * 128 + (n - 128)];
    __nv_bfloat16 h = __float2bfloat16(v);
    g_Whi[i] = h;
    g_Wlo[i] = __float2bfloat16(v - __bfloat162float(h));
}

// ---------------- HMMA GEMM (split-bf16, 3 terms) + logits epilogue ----------
#define APAD 40
#define BPAD 136

__global__ __launch_bounds__(256) void gemm_hmma_kernel(
        const float* __restrict__ x,
        const float* __restrict__ as0, const float* __restrict__ ad0,
        const float* __restrict__ as1, const float* __restrict__ ad1) {
    __shared__ __nv_bfloat16 sAh[128][APAD];
    __shared__ __nv_bfloat16 sAl[128][APAD];
    __shared__ __nv_bfloat16 sBh[32][BPAD];
    __shared__ __nv_bfloat16 sBl[32][BPAD];

    int tid  = threadIdx.x;
    int wid  = tid >> 5;
    int lane = tid & 31;
    int m0   = blockIdx.x * 128;
    int half = blockIdx.y;
    int m0w  = (wid >> 1) * 32;
    int n0w  = (wid & 1) * 64;

    float acc[2][8][4];
#pragma unroll
    for (int a = 0; a < 2; a++)
#pragma unroll
        for (int b = 0; b < 8; b++)
#pragma unroll
            for (int c = 0; c < 4; c++) acc[a][b][c] = 0.f;

    int arow = tid >> 1, akb = (tid & 1) * 16;
    bool aok = (m0 + arow) < N_NODES;
    int bk = tid >> 3, bnb = (tid & 7) * 16;

    int a_roff = ((lane >> 3) & 1) * 8 + (lane & 7);
    int a_coff = ((lane >> 4) & 1) * 8;
    int b_koff = ((lane >> 3) & 1) * 8 + (lane & 7);
    int b_noff = ((lane >> 4) & 1) * 8;

    for (int kc = 0; kc < 8; kc++) {
        if (kc > 0) __syncthreads();
        {
            const float* src = x + (size_t)(m0 + arow) * 256 + kc * 32 + akb;
#pragma unroll
            for (int i = 0; i < 16; i += 4) {
                float4 v = aok ? *(const float4*)(src + i)
                               : make_float4(0.f, 0.f, 0.f, 0.f);
                float fv[4] = {v.x, v.y, v.z, v.w};
                uint32_t ph[2], pl[2];
#pragma unroll
                for (int j = 0; j < 2; j++) {
                    __nv_bfloat16 h0 = __float2bfloat16(fv[2*j]);
                    __nv_bfloat16 h1 = __float2bfloat16(fv[2*j+1]);
                    __nv_bfloat16 l0 = __float2bfloat16(fv[2*j]   - __bfloat162float(h0));
                    __nv_bfloat16 l1 = __float2bfloat16(fv[2*j+1] - __bfloat162float(h1));
                    ph[j] = (uint32_t)__bfloat16_as_ushort(h0)
                          | ((uint32_t)__bfloat16_as_ushort(h1) << 16);
                    pl[j] = (uint32_t)__bfloat16_as_ushort(l0)
                          | ((uint32_t)__bfloat16_as_ushort(l1) << 16);
                }
                *(uint2*)&sAh[arow][akb + i] = make_uint2(ph[0], ph[1]);
                *(uint2*)&sAl[arow][akb + i] = make_uint2(pl[0], pl[1]);
            }
        }
        {
            const __nv_bfloat16* wh = g_Whi + (size_t)(kc * 32 + bk) * 256 + half * 128 + bnb;
            const __nv_bfloat16* wl = g_Wlo + (size_t)(kc * 32 + bk) * 256 + half * 128 + bnb;
            uint4 vh0 = *(const uint4*)wh;
            uint4 vh1 = *(const uint4*)(wh + 8);
            uint4 vl0 = *(const uint4*)wl;
            uint4 vl1 = *(const uint4*)(wl + 8);
            *(uint4*)&sBh[bk][bnb]     = vh0;
            *(uint4*)&sBh[bk][bnb + 8] = vh1;
            *(uint4*)&sBl[bk][bnb]     = vl0;
            *(uint4*)&sBl[bk][bnb + 8] = vl1;
        }
        __syncthreads();

#pragma unroll
        for (int ks = 0; ks < 2; ks++) {
            int k0 = ks * 16;
            uint32_t ah[2][4], al[2][4], bb[4][4];
#pragma unroll
            for (int mt = 0; mt < 2; mt++) {
                uint32_t adrh = smem_u32(&sAh[m0w + mt * 16 + a_roff][k0 + a_coff]);
                asm volatile("ldmatrix.sync.aligned.m8n8.x4.shared.b16 {%0,%1,%2,%3}, [%4];"
                    : "=r"(ah[mt][0]), "=r"(ah[mt][1]), "=r"(ah[mt][2]), "=r"(ah[mt][3])
                    : "r"(adrh));
                uint32_t adrl = smem_u32(&sAl[m0w + mt * 16 + a_roff][k0 + a_coff]);
                asm volatile("ldmatrix.sync.aligned.m8n8.x4.shared.b16 {%0,%1,%2,%3}, [%4];"
                    : "=r"(al[mt][0]), "=r"(al[mt][1]), "=r"(al[mt][2]), "=r"(al[mt][3])
                    : "r"(adrl));
            }
#pragma unroll
            for (int p = 0; p < 4; p++) {
                uint32_t adr = smem_u32(&sBh[k0 + b_koff][n0w + p * 16 + b_noff]);
                asm volatile("ldmatrix.sync.aligned.m8n8.x4.trans.shared.b16 {%0,%1,%2,%3}, [%4];"
                    : "=r"(bb[p][0]), "=r"(bb[p][1]), "=r"(bb[p][2]), "=r"(bb[p][3])
                    : "r"(adr));
            }
#pragma unroll
            for (int mt = 0; mt < 2; mt++)
#pragma unroll
                for (int nt = 0; nt < 8; nt++) {
                    uint32_t b0 = bb[nt >> 1][(nt & 1) * 2];
                    uint32_t b1 = bb[nt >> 1][(nt & 1) * 2 + 1];
                    float* d = acc[mt][nt];
                    asm volatile(
                        "mma.sync.aligned.m16n8k16.row.col.f32.bf16.bf16.f32 "
                        "{%0,%1,%2,%3}, {%4,%5,%6,%7}, {%8,%9}, {%0,%1,%2,%3};"
                        : "+f"(d[0]), "+f"(d[1]), "+f"(d[2]), "+f"(d[3])
                        : "r"(ah[mt][0]), "r"(ah[mt][1]), "r"(ah[mt][2]), "r"(ah[mt][3]),
                          "r"(b0), "r"(b1));
                    asm volatile(
                        "mma.sync.aligned.m16n8k16.row.col.f32.bf16.bf16.f32 "
                        "{%0,%1,%2,%3}, {%4,%5,%6,%7}, {%8,%9}, {%0,%1,%2,%3};"
                        : "+f"(d[0]), "+f"(d[1]), "+f"(d[2]), "+f"(d[3])
                        : "r"(al[mt][0]), "r"(al[mt][1]), "r"(al[mt][2]), "r"(al[mt][3]),
                          "r"(b0), "r"(b1));
                }
#pragma unroll
            for (int p = 0; p < 4; p++) {
                uint32_t adr = smem_u32(&sBl[k0 + b_koff][n0w + p * 16 + b_noff]);
                asm volatile("ldmatrix.sync.aligned.m8n8.x4.trans.shared.b16 {%0,%1,%2,%3}, [%4];"
                    : "=r"(bb[p][0]), "=r"(bb[p][1]), "=r"(bb[p][2]), "=r"(bb[p][3])
                    : "r"(adr));
            }
#pragma unroll
            for (int mt = 0; mt < 2; mt++)
#pragma unroll
                for (int nt = 0; nt < 8; nt++) {
                    uint32_t b0 = bb[nt >> 1][(nt & 1) * 2];
                    uint32_t b1 = bb[nt >> 1][(nt & 1) * 2 + 1];
                    float* d = acc[mt][nt];
                    asm volatile(
                        "mma.sync.aligned.m16n8k16.row.col.f32.bf16.bf16.f32 "
                        "{%0,%1,%2,%3}, {%4,%5,%6,%7}, {%8,%9}, {%0,%1,%2,%3};"
                        : "+f"(d[0]), "+f"(d[1]), "+f"(d[2]), "+f"(d[3])
                        : "r"(ah[mt][0]), "r"(ah[mt][1]), "r"(ah[mt][2]), "r"(ah[mt][3]),
                          "r"(b0), "r"(b1));
                }
        }
    }

    // ---- epilogue: store xw + attention logits ----
#pragma unroll
    for (int mt = 0; mt < 2; mt++) {
        int r0 = m0 + m0w + mt * 16 + (lane >> 2);
        int r1 = r0 + 8;
        bool ok0 = r0 < N_NODES, ok1 = r1 < N_NODES;
#pragma unroll
        for (int nt = 0; nt < 8; nt++) {
            int col = half * 128 + n0w + nt * 8 + (lane & 3) * 2;
            if (ok0) *(float2*)&g_xw[(size_t)r0 * 256 + col] =
                make_float2(acc[mt][nt][0], acc[mt][nt][1]);
            if (ok1) *(float2*)&g_xw[(size_t)r1 * 256 + col] =
                make_float2(acc[mt][nt][2], acc[mt][nt][3]);
        }
    }

    const float* asv = half ? as1 : as0;
    const float* adv = half ? ad1 : ad0;
    float asr[16], adr_[16];
#pragma unroll
    for (int nt = 0; nt < 8; nt++) {
        int c = n0w + nt * 8 + (lane & 3) * 2;
        asr[nt * 2]     = asv[c];
        asr[nt * 2 + 1] = asv[c + 1];
        adr_[nt * 2]     = adv[c];
        adr_[nt * 2 + 1] = adv[c + 1];
    }
#pragma unroll
    for (int mt = 0; mt < 2; mt++) {
#pragma unroll
        for (int rh = 0; rh < 2; rh++) {
            float ps[4] = {0.f, 0.f, 0.f, 0.f};
            float pd[4] = {0.f, 0.f, 0.f, 0.f};
#pragma unroll
            for (int nt = 0; nt < 8; nt++) {
                int h = nt >> 1;
                float a0 = acc[mt][nt][rh * 2];
                float a1 = acc[mt][nt][rh * 2 + 1];
                ps[h] += a0 * asr[nt * 2] + a1 * asr[nt * 2 + 1];
                pd[h] += a0 * adr_[nt * 2] + a1 * adr_[nt * 2 + 1];
            }
#pragma unroll
            for (int off = 1; off < 4; off <<= 1) {
#pragma unroll
                for (int h = 0; h < 4; h++) {
                    ps[h] += __shfl_xor_sync(0xffffffffu, ps[h], off);
                    pd[h] += __shfl_xor_sync(0xffffffffu, pd[h], off);
                }
            }
            int r = m0 + m0w + mt * 16 + rh * 8 + (lane >> 2);
            if ((lane & 3) == 0 && r < N_NODES) {
#pragma unroll
                for (int h = 0; h < 4; h++) {
                    int gh = (n0w >> 4) + h;
                    g_att[r * 32 + half * 16 + gh]     = ps[h];
                    g_att[r * 32 + half * 16 + 8 + gh] = pd[h];
                }
            }
        }
    }
}

// ---------------- zero degree counters ---------------------------------------
__global__ void zero_kernel() {
    int i = blockIdx.x * blockDim.x + threadIdx.x;
    if (i < TWO_N) g_deg[i] = 0;
}

// ---------------- count in-degrees (both hops) -------------------------------
__global__ void count_kernel(const int* __restrict__ row,
                             const int* __restrict__ col) {
    int e = blockIdx.x * blockDim.x + threadIdx.x;
    if (e >= N_EDGES) return;
    int d0 = col[e];
    atomicAdd(&g_deg[d0], 1);
    int d1 = col[d0];
    atomicAdd(&g_deg[N_NODES + d1], 1);
}

// ---------------- exclusive scan (3 stages) ----------------------------------
__global__ void scanA_kernel() {
    __shared__ int sh[SCAN_BLK];
    int t = threadIdx.x;
    int i = blockIdx.x * SCAN_BLK + t;
    int v = (i < TWO_N) ? g_deg[i] : 0;
    sh[t] = v;
    __syncthreads();
    for (int off = 1; off < SCAN_BLK; off <<= 1) {
        int add = (t >= off) ? sh[t - off] : 0;
        __syncthreads();
        sh[t] += add;
        __syncthreads();
    }
    if (i < TWO_N) g_off[i] = sh[t] - v;
    if (t == SCAN_BLK - 1) g_bsum[blockIdx.x] = sh[SCAN_BLK - 1];
}

__global__ void scanB_kernel() {
    __shared__ int sh[128];
    int t = threadIdx.x;
    int v = (t < SCAN_NBLK) ? g_bsum[t] : 0;
    sh[t] = v;
    __syncthreads();
    for (int off = 1; off < 128; off <<= 1) {
        int add = (t >= off) ? sh[t - off] : 0;
        __syncthreads();
        sh[t] += add;
        __syncthreads();
    }
    if (t < SCAN_NBLK) g_bsum_scan[t] = sh[t] - v;
}

__global__ void scanC_kernel() {
    int i = blockIdx.x * SCAN_BLK + threadIdx.x;
    if (i < TWO_N) {
        int v = g_off[i] + g_bsum_scan[blockIdx.x];
        g_off[i] = v;
        g_cur[i] = v;
    }
    if (i == 0) g_off[TWO_N] = TWO_E;
}

// ---------------- scatter sources into CSR -----------------------------------
__global__ void scatter_kernel(const int* __restrict__ row,
                               const int* __restrict__ col) {
    int e = blockIdx.x * blockDim.x + threadIdx.x;
    if (e >= N_EDGES) return;
    int r0 = row[e];
    int d0 = col[e];
    int p = atomicAdd(&g_cur[d0], 1);
    g_srcarr[p] = r0;
    int r1 = row[d0];
    int d1 = col[d0];
    p = atomicAdd(&g_cur[N_NODES + d1], 1);
    g_srcarr[p] = r1;
}

// ---------------- fused aggregation + residual + LayerNorm -------------------
__global__ void agg_ln_kernel(const float* __restrict__ b0,
                              const float* __restrict__ b1,
                              const float* __restrict__ x,
                              const float* __restrict__ gamma,
                              const float* __restrict__ beta,
                              float* __restrict__ out) {
    int n = (blockIdx.x * blockDim.x + threadIdx.x) >> 5;
    if (n >= N_NODES) return;
    int lane = threadIdx.x & 31;
    int head = lane >> 2;
    int c0 = lane * 4;

    // ---- hop 0 ----
    float ad = g_att[n * 32 + 8 + head];
    float t  = g_att[n * 32 + head] + ad;
    t = (t > 0.f) ? t : 0.2f * t;
    float p = __expf(t);
    float sum0 = p;
    float4 v = *(const float4*)&g_xw[n * 256 + c0];
    float4 acc0 = make_float4(p * v.x, p * v.y, p * v.z, p * v.w);
    int je = g_off[n + 1];
    for (int j = g_off[n]; j < je; j++) {
        int src = g_srcarr[j];
        float tt = g_att[src * 32 + head] + ad;
        tt = (tt > 0.f) ? tt : 0.2f * tt;
        float pp = __expf(tt);
        sum0 += pp;
        float4 w = *(const float4*)&g_xw[src * 256 + c0];
        acc0.x += pp * w.x; acc0.y += pp * w.y;
        acc0.z += pp * w.z; acc0.w += pp * w.w;
    }

    // ---- hop 1 (self doubled: reference appends self-loops twice) ----
    ad = g_att[n * 32 + 24 + head];
    t  = g_att[n * 32 + 16 + head] + ad;
    t = (t > 0.f) ? t : 0.2f * t;
    p = 2.0f * __expf(t);
    float sum1 = p;
    v = *(const float4*)&g_xw[n * 256 + 128 + c0];
    float4 acc1 = make_float4(p * v.x, p * v.y, p * v.z, p * v.w);
    je = g_off[N_NODES + n + 1];
    for (int j = g_off[N_NODES + n]; j < je; j++) {
        int src = g_srcarr[j];
        float tt = g_att[src * 32 + 16 + head] + ad;
        tt = (tt > 0.f) ? tt : 0.2f * tt;
        float pp = __expf(tt);
        sum1 += pp;
        float4 w = *(const float4*)&g_xw[src * 256 + 128 + c0];
        acc1.x += pp * w.x; acc1.y += pp * w.y;
        acc1.z += pp * w.z; acc1.w += pp * w.w;
    }

    // ---- bias + residual + LN ----
    float i0 = 1.f / sum0, i1 = 1.f / sum1;
    float4 bb0 = *(const float4*)&b0[c0];
    float4 bb1 = *(const float4*)&b1[c0];
    float4 x0 = *(const float4*)&x[n * 256 + c0];
    float4 x1 = *(const float4*)&x[n * 256 + 128 + c0];
    float vv[8];
    vv[0] = acc0.x * i0 + bb0.x + x0.x;
    vv[1] = acc0.y * i0 + bb0.y + x0.y;
    vv[2] = acc0.z * i0 + bb0.z + x0.z;
    vv[3] = acc0.w * i0 + bb0.w + x0.w;
    vv[4] = acc1.x * i1 + bb1.x + x1.x;
    vv[5] = acc1.y * i1 + bb1.y + x1.y;
    vv[6] = acc1.z * i1 + bb1.z + x1.z;
    vv[7] = acc1.w * i1 + bb1.w + x1.w;

    float s = 0.f, s2 = 0.f;
#pragma unroll
    for (int i = 0; i < 8; i++) { s += vv[i]; s2 += vv[i] * vv[i]; }
#pragma unroll
    for (int off = 16; off > 0; off >>= 1) {
        s  += __shfl_xor_sync(0xffffffffu, s, off);
        s2 += __shfl_xor_sync(0xffffffffu, s2, off);
    }
    float mean = s * (1.f / 256.f);
    float var  = s2 * (1.f / 256.f) - mean * mean;
    float rs   = rsqrtf(var + 1e-5f);

    float4 g0 = *(const float4*)&gamma[c0];
    float4 g1 = *(const float4*)&gamma[128 + c0];
    float4 be0 = *(const float4*)&beta[c0];
    float4 be1 = *(const float4*)&beta[128 + c0];
    float4 o0, o1;
    o0.x = (vv[0] - mean) * rs * g0.x + be0.x;
    o0.y = (vv[1] - mean) * rs * g0.y + be0.y;
    o0.z = (vv[2] - mean) * rs * g0.z + be0.z;
    o0.w = (vv[3] - mean) * rs * g0.w + be0.w;
    o1.x = (vv[4] - mean) * rs * g1.x + be1.x;
    o1.y = (vv[5] - mean) * rs * g1.y + be1.y;
    o1.z = (vv[6] - mean) * rs * g1.z + be1.z;
    o1.w = (vv[7] - mean) * rs * g1.w + be1.w;
    *(float4*)&out[n * 256 + c0]       = o0;
    *(float4*)&out[n * 256 + 128 + c0] = o1;
}

// ---------------- launch -----------------------------------------------------
extern "C" void kernel_launch(void* const* d_in, const int* in_sizes, int n_in,
                              void* d_out, int out_size) {
    const float* x     = (const float*)d_in[0];
    const int*   ei    = (const int*)d_in[1];
    const float* W0    = (const float*)d_in[2];
    const float* as0   = (const float*)d_in[3];
    const float* ad0   = (const float*)d_in[4];
    const float* b0    = (const float*)d_in[5];
    const float* W1    = (const float*)d_in[6];
    const float* as1   = (const float*)d_in[7];
    const float* ad1   = (const float*)d_in[8];
    const float* b1    = (const float*)d_in[9];
    const float* gamma = (const float*)d_in[10];
    const float* beta  = (const float*)d_in[11];
    float* out = (float*)d_out;

    const int* row = ei;
    const int* col = ei + N_EDGES;

    zero_kernel<<<(TWO_N + 255) / 256, 256>>>();
    wsplit_kernel<<<256, 256>>>(W0, W1);
    gemm_hmma_kernel<<<dim3((N_NODES + 127) / 128, 2), 256>>>(x, as0, ad0, as1, ad1);
    count_kernel<<<(N_EDGES + 255) / 256, 256>>>(row, col);
    scanA_kernel<<<SCAN_NBLK, SCAN_BLK>>>();
    scanB_kernel<<<1, 128>>>();
    scanC_kernel<<<SCAN_NBLK, SCAN_BLK>>>();
    scatter_kernel<<<(N_EDGES + 255) / 256, 256>>>(row, col);
    agg_ln_kernel<<<(N_NODES * 32 + 255) / 256, 256>>>(b0, b1, x, gamma, beta, out);
}

// round 11
// speedup vs baseline: 1.7508x; 1.1707x over previous
#include <cuda_runtime.h>
#include <cuda_bf16.h>
#include <cstdint>

#define N_NODES 50000
#define N_EDGES 800000
#define TWO_N   100000
#define TWO_E   1600000
#define SCAN_BLK 1024
#define SCAN_NBLK ((TWO_N + SCAN_BLK - 1) / SCAN_BLK)   // 98

// ---------------- scratch ----------------------------------------------------
__device__ __align__(16) float g_xw[N_NODES * 256];   // x @ [W0 | W1]
__device__ __align__(16) float g_att[N_NODES * 32];   // [s0(8) d0(8) s1(8) d1(8)]
__device__ __align__(16) __nv_bfloat16 g_Whi[256 * 256];  // [k][n] n: [W0|W1]
__device__ __align__(16) __nv_bfloat16 g_Wlo[256 * 256];
__device__ int   g_deg[TWO_N];     // [0,N): deg0 (hop-0 in-degree); [N,2N): deg1 (collapsed)
__device__ int   g_off[TWO_N + 1];
__device__ int   g_cur[TWO_N];
__device__ int   g_srcarr[TWO_E];  // hop0: src; hop1: src | (weight<<16)
__device__ int   g_bsum[SCAN_NBLK];
__device__ int   g_bsum_scan[SCAN_NBLK];

__device__ __forceinline__ uint32_t smem_u32(const void* p) {
    uint32_t a;
    asm("{ .reg .u64 t; cvta.to.shared.u64 t, %1; cvt.u32.u64 %0, t; }"
        : "=r"(a) : "l"(p));
    return a;
}

// ---------------- W split kernel ---------------------------------------------
__global__ void wsplit_kernel(const float* __restrict__ W0,
                              const float* __restrict__ W1) {
    int i = blockIdx.x * 256 + threadIdx.x;
    int k = i >> 8, n = i & 255;
    float v = (n < 128) ? W0[k * 128 + n] : W1[k * 128 + (n - 128)];
    __nv_bfloat16 h = __float2bfloat16(v);
    g_Whi[i] = h;
    g_Wlo[i] = __float2bfloat16(v - __bfloat162float(h));
}

// ---------------- HMMA GEMM (split-bf16, 3 terms) + logits epilogue ----------
#define APAD 40
#define BPAD 136

__global__ __launch_bounds__(256) void gemm_hmma_kernel(
        const float* __restrict__ x,
        const float* __restrict__ as0, const float* __restrict__ ad0,
        const float* __restrict__ as1, const float* __restrict__ ad1) {
    __shared__ __nv_bfloat16 sAh[128][APAD];
    __shared__ __nv_bfloat16 sAl[128][APAD];
    __shared__ __nv_bfloat16 sBh[32][BPAD];
    __shared__ __nv_bfloat16 sBl[32][BPAD];

    int tid  = threadIdx.x;
    int wid  = tid >> 5;
    int lane = tid & 31;
    int m0   = blockIdx.x * 128;
    int half = blockIdx.y;
    int m0w  = (wid >> 1) * 32;
    int n0w  = (wid & 1) * 64;

    float acc[2][8][4];
#pragma unroll
    for (int a = 0; a < 2; a++)
#pragma unroll
        for (int b = 0; b < 8; b++)
#pragma unroll
            for (int c = 0; c < 4; c++) acc[a][b][c] = 0.f;

    int arow = tid >> 1, akb = (tid & 1) * 16;
    bool aok = (m0 + arow) < N_NODES;
    int bk = tid >> 3, bnb = (tid & 7) * 16;

    int a_roff = ((lane >> 3) & 1) * 8 + (lane & 7);
    int a_coff = ((lane >> 4) & 1) * 8;
    int b_koff = ((lane >> 3) & 1) * 8 + (lane & 7);
    int b_noff = ((lane >> 4) & 1) * 8;

    for (int kc = 0; kc < 8; kc++) {
        if (kc > 0) __syncthreads();
        {
            const float* src = x + (size_t)(m0 + arow) * 256 + kc * 32 + akb;
#pragma unroll
            for (int i = 0; i < 16; i += 4) {
                float4 v = aok ? *(const float4*)(src + i)
                               : make_float4(0.f, 0.f, 0.f, 0.f);
                float fv[4] = {v.x, v.y, v.z, v.w};
                uint32_t ph[2], pl[2];
#pragma unroll
                for (int j = 0; j < 2; j++) {
                    __nv_bfloat16 h0 = __float2bfloat16(fv[2*j]);
                    __nv_bfloat16 h1 = __float2bfloat16(fv[2*j+1]);
                    __nv_bfloat16 l0 = __float2bfloat16(fv[2*j]   - __bfloat162float(h0));
                    __nv_bfloat16 l1 = __float2bfloat16(fv[2*j+1] - __bfloat162float(h1));
                    ph[j] = (uint32_t)__bfloat16_as_ushort(h0)
                          | ((uint32_t)__bfloat16_as_ushort(h1) << 16);
                    pl[j] = (uint32_t)__bfloat16_as_ushort(l0)
                          | ((uint32_t)__bfloat16_as_ushort(l1) << 16);
                }
                *(uint2*)&sAh[arow][akb + i] = make_uint2(ph[0], ph[1]);
                *(uint2*)&sAl[arow][akb + i] = make_uint2(pl[0], pl[1]);
            }
        }
        {
            const __nv_bfloat16* wh = g_Whi + (size_t)(kc * 32 + bk) * 256 + half * 128 + bnb;
            const __nv_bfloat16* wl = g_Wlo + (size_t)(kc * 32 + bk) * 256 + half * 128 + bnb;
            uint4 vh0 = *(const uint4*)wh;
            uint4 vh1 = *(const uint4*)(wh + 8);
            uint4 vl0 = *(const uint4*)wl;
            uint4 vl1 = *(const uint4*)(wl + 8);
            *(uint4*)&sBh[bk][bnb]     = vh0;
            *(uint4*)&sBh[bk][bnb + 8] = vh1;
            *(uint4*)&sBl[bk][bnb]     = vl0;
            *(uint4*)&sBl[bk][bnb + 8] = vl1;
        }
        __syncthreads();

#pragma unroll
        for (int ks = 0; ks < 2; ks++) {
            int k0 = ks * 16;
            uint32_t ah[2][4], al[2][4], bb[4][4];
#pragma unroll
            for (int mt = 0; mt < 2; mt++) {
                uint32_t adrh = smem_u32(&sAh[m0w + mt * 16 + a_roff][k0 + a_coff]);
                asm volatile("ldmatrix.sync.aligned.m8n8.x4.shared.b16 {%0,%1,%2,%3}, [%4];"
                    : "=r"(ah[mt][0]), "=r"(ah[mt][1]), "=r"(ah[mt][2]), "=r"(ah[mt][3])
                    : "r"(adrh));
                uint32_t adrl = smem_u32(&sAl[m0w + mt * 16 + a_roff][k0 + a_coff]);
                asm volatile("ldmatrix.sync.aligned.m8n8.x4.shared.b16 {%0,%1,%2,%3}, [%4];"
                    : "=r"(al[mt][0]), "=r"(al[mt][1]), "=r"(al[mt][2]), "=r"(al[mt][3])
                    : "r"(adrl));
            }
#pragma unroll
            for (int p = 0; p < 4; p++) {
                uint32_t adr = smem_u32(&sBh[k0 + b_koff][n0w + p * 16 + b_noff]);
                asm volatile("ldmatrix.sync.aligned.m8n8.x4.trans.shared.b16 {%0,%1,%2,%3}, [%4];"
                    : "=r"(bb[p][0]), "=r"(bb[p][1]), "=r"(bb[p][2]), "=r"(bb[p][3])
                    : "r"(adr));
            }
#pragma unroll
            for (int mt = 0; mt < 2; mt++)
#pragma unroll
                for (int nt = 0; nt < 8; nt++) {
                    uint32_t b0 = bb[nt >> 1][(nt & 1) * 2];
                    uint32_t b1 = bb[nt >> 1][(nt & 1) * 2 + 1];
                    float* d = acc[mt][nt];
                    asm volatile(
                        "mma.sync.aligned.m16n8k16.row.col.f32.bf16.bf16.f32 "
                        "{%0,%1,%2,%3}, {%4,%5,%6,%7}, {%8,%9}, {%0,%1,%2,%3};"
                        : "+f"(d[0]), "+f"(d[1]), "+f"(d[2]), "+f"(d[3])
                        : "r"(ah[mt][0]), "r"(ah[mt][1]), "r"(ah[mt][2]), "r"(ah[mt][3]),
                          "r"(b0), "r"(b1));
                    asm volatile(
                        "mma.sync.aligned.m16n8k16.row.col.f32.bf16.bf16.f32 "
                        "{%0,%1,%2,%3}, {%4,%5,%6,%7}, {%8,%9}, {%0,%1,%2,%3};"
                        : "+f"(d[0]), "+f"(d[1]), "+f"(d[2]), "+f"(d[3])
                        : "r"(al[mt][0]), "r"(al[mt][1]), "r"(al[mt][2]), "r"(al[mt][3]),
                          "r"(b0), "r"(b1));
                }
#pragma unroll
            for (int p = 0; p < 4; p++) {
                uint32_t adr = smem_u32(&sBl[k0 + b_koff][n0w + p * 16 + b_noff]);
                asm volatile("ldmatrix.sync.aligned.m8n8.x4.trans.shared.b16 {%0,%1,%2,%3}, [%4];"
                    : "=r"(bb[p][0]), "=r"(bb[p][1]), "=r"(bb[p][2]), "=r"(bb[p][3])
                    : "r"(adr));
            }
#pragma unroll
            for (int mt = 0; mt < 2; mt++)
#pragma unroll
                for (int nt = 0; nt < 8; nt++) {
                    uint32_t b0 = bb[nt >> 1][(nt & 1) * 2];
                    uint32_t b1 = bb[nt >> 1][(nt & 1) * 2 + 1];
                    float* d = acc[mt][nt];
                    asm volatile(
                        "mma.sync.aligned.m16n8k16.row.col.f32.bf16.bf16.f32 "
                        "{%0,%1,%2,%3}, {%4,%5,%6,%7}, {%8,%9}, {%0,%1,%2,%3};"
                        : "+f"(d[0]), "+f"(d[1]), "+f"(d[2]), "+f"(d[3])
                        : "r"(ah[mt][0]), "r"(ah[mt][1]), "r"(ah[mt][2]), "r"(ah[mt][3]),
                          "r"(b0), "r"(b1));
                }
        }
    }

    // ---- epilogue: store xw + attention logits ----
#pragma unroll
    for (int mt = 0; mt < 2; mt++) {
        int r0 = m0 + m0w + mt * 16 + (lane >> 2);
        int r1 = r0 + 8;
        bool ok0 = r0 < N_NODES, ok1 = r1 < N_NODES;
#pragma unroll
        for (int nt = 0; nt < 8; nt++) {
            int col = half * 128 + n0w + nt * 8 + (lane & 3) * 2;
            if (ok0) *(float2*)&g_xw[(size_t)r0 * 256 + col] =
                make_float2(acc[mt][nt][0], acc[mt][nt][1]);
            if (ok1) *(float2*)&g_xw[(size_t)r1 * 256 + col] =
                make_float2(acc[mt][nt][2], acc[mt][nt][3]);
        }
    }

    const float* asv = half ? as1 : as0;
    const float* adv = half ? ad1 : ad0;
    float asr[16], adr_[16];
#pragma unroll
    for (int nt = 0; nt < 8; nt++) {
        int c = n0w + nt * 8 + (lane & 3) * 2;
        asr[nt * 2]     = asv[c];
        asr[nt * 2 + 1] = asv[c + 1];
        adr_[nt * 2]     = adv[c];
        adr_[nt * 2 + 1] = adv[c + 1];
    }
#pragma unroll
    for (int mt = 0; mt < 2; mt++) {
#pragma unroll
        for (int rh = 0; rh < 2; rh++) {
            float ps[4] = {0.f, 0.f, 0.f, 0.f};
            float pd[4] = {0.f, 0.f, 0.f, 0.f};
#pragma unroll
            for (int nt = 0; nt < 8; nt++) {
                int h = nt >> 1;
                float a0 = acc[mt][nt][rh * 2];
                float a1 = acc[mt][nt][rh * 2 + 1];
                ps[h] += a0 * asr[nt * 2] + a1 * asr[nt * 2 + 1];
                pd[h] += a0 * adr_[nt * 2] + a1 * adr_[nt * 2 + 1];
            }
#pragma unroll
            for (int off = 1; off < 4; off <<= 1) {
#pragma unroll
                for (int h = 0; h < 4; h++) {
                    ps[h] += __shfl_xor_sync(0xffffffffu, ps[h], off);
                    pd[h] += __shfl_xor_sync(0xffffffffu, pd[h], off);
                }
            }
            int r = m0 + m0w + mt * 16 + rh * 8 + (lane >> 2);
            if ((lane & 3) == 0 && r < N_NODES) {
#pragma unroll
                for (int h = 0; h < 4; h++) {
                    int gh = (n0w >> 4) + h;
                    g_att[r * 32 + half * 16 + gh]     = ps[h];
                    g_att[r * 32 + half * 16 + 8 + gh] = pd[h];
                }
            }
        }
    }
}

// ---------------- zero degree counters ---------------------------------------
__global__ void zero_kernel() {
    int i = blockIdx.x * blockDim.x + threadIdx.x;
    if (i < TWO_N) g_deg[i] = 0;
}

// ---------------- count0: hop-0 in-degrees (coalesced col reads) -------------
__global__ void count0_kernel(const int* __restrict__ col) {
    int e = blockIdx.x * blockDim.x + threadIdx.x;
    if (e >= N_EDGES) return;
    atomicAdd(&g_deg[col[e]], 1);
}

// ---------------- count1: collapsed hop-1 degrees ----------------------------
// hop-2 edges are (row[c], col[c]) for c = col[e] in [0, N); multiplicity of
// group c is deg0[c]. One entry per c with deg0[c] > 0.
__global__ void count1_kernel(const int* __restrict__ col) {
    int c = blockIdx.x * blockDim.x + threadIdx.x;
    if (c >= N_NODES) return;
    if (g_deg[c] > 0) atomicAdd(&g_deg[N_NODES + col[c]], 1);
}

// ---------------- exclusive scan (3 stages) ----------------------------------
__global__ void scanA_kernel() {
    __shared__ int sh[SCAN_BLK];
    int t = threadIdx.x;
    int i = blockIdx.x * SCAN_BLK + t;
    int v = (i < TWO_N) ? g_deg[i] : 0;
    sh[t] = v;
    __syncthreads();
    for (int off = 1; off < SCAN_BLK; off <<= 1) {
        int add = (t >= off) ? sh[t - off] : 0;
        __syncthreads();
        sh[t] += add;
        __syncthreads();
    }
    if (i < TWO_N) g_off[i] = sh[t] - v;
    if (t == SCAN_BLK - 1) g_bsum[blockIdx.x] = sh[SCAN_BLK - 1];
}

__global__ void scanB_kernel() {
    __shared__ int sh[128];
    int t = threadIdx.x;
    int v = (t < SCAN_NBLK) ? g_bsum[t] : 0;
    sh[t] = v;
    __syncthreads();
    for (int off = 1; off < 128; off <<= 1) {
        int add = (t >= off) ? sh[t - off] : 0;
        __syncthreads();
        sh[t] += add;
        __syncthreads();
    }
    if (t < SCAN_NBLK) g_bsum_scan[t] = sh[t] - v;
}

__global__ void scanC_kernel() {
    int i = blockIdx.x * SCAN_BLK + threadIdx.x;
    if (i < TWO_N) {
        int v = g_off[i] + g_bsum_scan[blockIdx.x];
        g_off[i] = v;
        g_cur[i] = v;
        if (i == TWO_N - 1) g_off[TWO_N] = v + g_deg[i];   // true total
    }
}

// ---------------- scatter0: hop-0 edges --------------------------------------
__global__ void scatter0_kernel(const int* __restrict__ row,
                                const int* __restrict__ col) {
    int e = blockIdx.x * blockDim.x + threadIdx.x;
    if (e >= N_EDGES) return;
    int p = atomicAdd(&g_cur[col[e]], 1);
    g_srcarr[p] = row[e];
}

// ---------------- scatter1: collapsed hop-1 entries (src | weight<<16) -------
__global__ void scatter1_kernel(const int* __restrict__ row,
                                const int* __restrict__ col) {
    int c = blockIdx.x * blockDim.x + threadIdx.x;
    if (c >= N_NODES) return;
    int w = g_deg[c];
    if (w <= 0) return;
    int p = atomicAdd(&g_cur[N_NODES + col[c]], 1);
    g_srcarr[p] = row[c] | (w << 16);    // row[c] < 50000 < 65536; w small
}

// ---------------- fused aggregation + residual + LayerNorm -------------------
__global__ void agg_ln_kernel(const float* __restrict__ b0,
                              const float* __restrict__ b1,
                              const float* __restrict__ x,
                              const float* __restrict__ gamma,
                              const float* __restrict__ beta,
                              float* __restrict__ out) {
    int n = (blockIdx.x * blockDim.x + threadIdx.x) >> 5;
    if (n >= N_NODES) return;
    int lane = threadIdx.x & 31;
    int head = lane >> 2;
    int c0 = lane * 4;

    // ---- hop 0 ----
    float ad = g_att[n * 32 + 8 + head];
    float t  = g_att[n * 32 + head] + ad;
    t = (t > 0.f) ? t : 0.2f * t;
    float p = __expf(t);
    float sum0 = p;
    float4 v = *(const float4*)&g_xw[n * 256 + c0];
    float4 acc0 = make_float4(p * v.x, p * v.y, p * v.z, p * v.w);
    int je = g_off[n + 1];
    for (int j = g_off[n]; j < je; j++) {
        int src = g_srcarr[j];
        float tt = g_att[src * 32 + head] + ad;
        tt = (tt > 0.f) ? tt : 0.2f * tt;
        float pp = __expf(tt);
        sum0 += pp;
        float4 w = *(const float4*)&g_xw[src * 256 + c0];
        acc0.x += pp * w.x; acc0.y += pp * w.y;
        acc0.z += pp * w.z; acc0.w += pp * w.w;
    }

    // ---- hop 1 (collapsed weighted entries; self doubled) ----
    ad = g_att[n * 32 + 24 + head];
    t  = g_att[n * 32 + 16 + head] + ad;
    t = (t > 0.f) ? t : 0.2f * t;
    p = 2.0f * __expf(t);
    float sum1 = p;
    v = *(const float4*)&g_xw[n * 256 + 128 + c0];
    float4 acc1 = make_float4(p * v.x, p * v.y, p * v.z, p * v.w);
    je = g_off[N_NODES + n + 1];
    for (int j = g_off[N_NODES + n]; j < je; j++) {
        int ent = g_srcarr[j];
        int src = ent & 0xFFFF;
        float wgt = (float)(ent >> 16);
        float tt = g_att[src * 32 + 16 + head] + ad;
        tt = (tt > 0.f) ? tt : 0.2f * tt;
        float pp = wgt * __expf(tt);
        sum1 += pp;
        float4 w = *(const float4*)&g_xw[src * 256 + 128 + c0];
        acc1.x += pp * w.x; acc1.y += pp * w.y;
        acc1.z += pp * w.z; acc1.w += pp * w.w;
    }

    // ---- bias + residual + LN ----
    float i0 = 1.f / sum0, i1 = 1.f / sum1;
    float4 bb0 = *(const float4*)&b0[c0];
    float4 bb1 = *(const float4*)&b1[c0];
    float4 x0 = *(const float4*)&x[n * 256 + c0];
    float4 x1 = *(const float4*)&x[n * 256 + 128 + c0];
    float vv[8];
    vv[0] = acc0.x * i0 + bb0.x + x0.x;
    vv[1] = acc0.y * i0 + bb0.y + x0.y;
    vv[2] = acc0.z * i0 + bb0.z + x0.z;
    vv[3] = acc0.w * i0 + bb0.w + x0.w;
    vv[4] = acc1.x * i1 + bb1.x + x1.x;
    vv[5] = acc1.y * i1 + bb1.y + x1.y;
    vv[6] = acc1.z * i1 + bb1.z + x1.z;
    vv[7] = acc1.w * i1 + bb1.w + x1.w;

    float s = 0.f, s2 = 0.f;
#pragma unroll
    for (int i = 0; i < 8; i++) { s += vv[i]; s2 += vv[i] * vv[i]; }
#pragma unroll
    for (int off = 16; off > 0; off >>= 1) {
        s  += __shfl_xor_sync(0xffffffffu, s, off);
        s2 += __shfl_xor_sync(0xffffffffu, s2, off);
    }
    float mean = s * (1.f / 256.f);
    float var  = s2 * (1.f / 256.f) - mean * mean;
    float rs   = rsqrtf(var + 1e-5f);

    float4 g0 = *(const float4*)&gamma[c0];
    float4 g1 = *(const float4*)&gamma[128 + c0];
    float4 be0 = *(const float4*)&beta[c0];
    float4 be1 = *(const float4*)&beta[128 + c0];
    float4 o0, o1;
    o0.x = (vv[0] - mean) * rs * g0.x + be0.x;
    o0.y = (vv[1] - mean) * rs * g0.y + be0.y;
    o0.z = (vv[2] - mean) * rs * g0.z + be0.z;
    o0.w = (vv[3] - mean) * rs * g0.w + be0.w;
    o1.x = (vv[4] - mean) * rs * g1.x + be1.x;
    o1.y = (vv[5] - mean) * rs * g1.y + be1.y;
    o1.z = (vv[6] - mean) * rs * g1.z + be1.z;
    o1.w = (vv[7] - mean) * rs * g1.w + be1.w;
    *(float4*)&out[n * 256 + c0]       = o0;
    *(float4*)&out[n * 256 + 128 + c0] = o1;
}

// ---------------- launch -----------------------------------------------------
extern "C" void kernel_launch(void* const* d_in, const int* in_sizes, int n_in,
                              void* d_out, int out_size) {
    const float* x     = (const float*)d_in[0];
    const int*   ei    = (const int*)d_in[1];
    const float* W0    = (const float*)d_in[2];
    const float* as0   = (const float*)d_in[3];
    const float* ad0   = (const float*)d_in[4];
    const float* b0    = (const float*)d_in[5];
    const float* W1    = (const float*)d_in[6];
    const float* as1   = (const float*)d_in[7];
    const float* ad1   = (const float*)d_in[8];
    const float* b1    = (const float*)d_in[9];
    const float* gamma = (const float*)d_in[10];
    const float* beta  = (const float*)d_in[11];
    float* out = (float*)d_out;

    const int* row = ei;
    const int* col = ei + N_EDGES;

    zero_kernel<<<(TWO_N + 255) / 256, 256>>>();
    wsplit_kernel<<<256, 256>>>(W0, W1);
    gemm_hmma_kernel<<<dim3((N_NODES + 127) / 128, 2), 256>>>(x, as0, ad0, as1, ad1);
    count0_kernel<<<(N_EDGES + 255) / 256, 256>>>(col);
    count1_kernel<<<(N_NODES + 255) / 256, 256>>>(col);
    scanA_kernel<<<SCAN_NBLK, SCAN_BLK>>>();
    scanB_kernel<<<1, 128>>>();
    scanC_kernel<<<SCAN_NBLK, SCAN_BLK>>>();
    scatter0_kernel<<<(N_EDGES + 255) / 256, 256>>>(row, col);
    scatter1_kernel<<<(N_NODES + 255) / 256, 256>>>(row, col);
    agg_ln_kernel<<<(N_NODES * 32 + 255) / 256, 256>>>(b0, b1, x, gamma, beta, out);
}